// round 7
// baseline (speedup 1.0000x reference)
#include <cuda_runtime.h>

// LSTMOptimizer: per-element (N=524288) single LSTMCell step (input 4, H=128)
// + Linear(H,1) head. One warp per element-quad; lane owns 4 hidden columns.
//
// R6 vs R5 (266us, latency-bound: occ 41%, DRAM 48%, issue 38%):
//  - FOUR elements per iteration: 8 front-batched 512B loads per warp
//    (~82KB in flight per SM vs 57KB) -> +43% memory concurrency
//  - __launch_bounds__(128,5), grid=740=148x5: one exact full wave
//  - guarded quad loop + per-element tail (N no longer divides the stride)
//  - keep: SMEM weight table, tanh.approx, __ldcs/__stcs streaming

namespace {

constexpr int HH = 128;
constexpr int WSLOTS = 21;  // float4 slots per lane: 16 W rows + 4 bias + 1 wup

__device__ __forceinline__ float tanhx(float x) {
    float y;
    asm("tanh.approx.f32 %0, %1;" : "=f"(y) : "f"(x));
    return y;
}
__device__ __forceinline__ float sigx(float z) {
    return fmaf(0.5f, tanhx(0.5f * z), 0.5f);
}

// Generic recurrent term (h != 0): exact shuffle-broadcast h @ W_hh.T.
// Warp-uniform entry (guarded by __any_sync result). Rare path.
__device__ __noinline__ void add_recurrent(float zf[16], float4 h4,
                                           const float* __restrict__ W_hh,
                                           int colbase) {
    #pragma unroll 1
    for (int src = 0; src < 32; ++src) {
        const float b0 = __shfl_sync(0xffffffffu, h4.x, src);
        const float b1 = __shfl_sync(0xffffffffu, h4.y, src);
        const float b2 = __shfl_sync(0xffffffffu, h4.z, src);
        const float b3 = __shfl_sync(0xffffffffu, h4.w, src);
        const int kk = src << 2;
        #pragma unroll
        for (int g = 0; g < 4; ++g) {
            #pragma unroll
            for (int k = 0; k < 4; ++k) {
                const float* wr = W_hh + (size_t)(g * HH + colbase + k) * HH + kk;
                float zz = zf[g * 4 + k];
                zz = fmaf(__ldg(wr + 0), b0, zz);
                zz = fmaf(__ldg(wr + 1), b1, zz);
                zz = fmaf(__ldg(wr + 2), b2, zz);
                zz = fmaf(__ldg(wr + 3), b3, zz);
                zf[g * 4 + k] = zz;
            }
        }
    }
}

// Activations + cell/hidden update + head partial dot for one element.
__device__ __forceinline__ float finish_elem(const float zf[16], float4 c4,
                                             float4 wup, float4& hn4, float4& cn4) {
    const float cin[4] = {c4.x, c4.y, c4.z, c4.w};
    const float wuk[4] = {wup.x, wup.y, wup.z, wup.w};
    float hn[4], cn[4];
    float acc = 0.0f;
    #pragma unroll
    for (int k = 0; k < 4; ++k) {
        const float iv = sigx(zf[0 * 4 + k]);
        const float fv = sigx(zf[1 * 4 + k]);
        const float gg = tanhx(zf[2 * 4 + k]);
        const float ov = sigx(zf[3 * 4 + k]);
        const float cc = fmaf(fv, cin[k], iv * gg);
        const float hh = ov * tanhx(cc);
        cn[k] = cc;
        hn[k] = hh;
        acc = fmaf(hh, wuk[k], acc);
    }
    hn4 = make_float4(hn[0], hn[1], hn[2], hn[3]);
    cn4 = make_float4(cn[0], cn[1], cn[2], cn[3]);
    return acc;
}

__global__ void __launch_bounds__(128, 5)
lstm_opt_kernel(const float* __restrict__ param, const float* __restrict__ grad,
                const float* __restrict__ hmat,  const float* __restrict__ cmat,
                const float* __restrict__ momentum, const float* __restrict__ prevu,
                const float* __restrict__ W_ih,  const float* __restrict__ W_hh,
                const float* __restrict__ b_ih,  const float* __restrict__ b_hh,
                const float* __restrict__ W_up,  const float* __restrict__ b_up,
                float* __restrict__ out_upd, float* __restrict__ out_h,
                float* __restrict__ out_c,   float* __restrict__ out_mom,
                int N)
{
    // Per-lane table (float4 slots):
    //   [0..15]  W_ih row (4 floats) for gate-row r = (q>>2)*128 + lane*4 + (q&3)
    //   [16..19] bias sums b_ih[r]+b_hh[r] for the 16 rows (4 per slot)
    //   [20]     W_up[lane*4 .. +3]
    __shared__ float4 wtab[32 * WSLOTS];

    for (int idx = threadIdx.x; idx < 32 * WSLOTS; idx += blockDim.x) {
        const int l = idx / WSLOTS;
        const int q = idx % WSLOTS;
        float4 v;
        if (q < 16) {
            const int r = (q >> 2) * HH + l * 4 + (q & 3);
            v = *reinterpret_cast<const float4*>(W_ih + 4 * r);
        } else if (q < 20) {
            const int g = q - 16;
            const int r0 = g * HH + l * 4;
            v = make_float4(b_ih[r0 + 0] + b_hh[r0 + 0],
                            b_ih[r0 + 1] + b_hh[r0 + 1],
                            b_ih[r0 + 2] + b_hh[r0 + 2],
                            b_ih[r0 + 3] + b_hh[r0 + 3]);
        } else {
            v = *reinterpret_cast<const float4*>(W_up + l * 4);
        }
        wtab[idx] = v;
    }
    __syncthreads();

    const int lane    = threadIdx.x & 31;
    const int warp    = blockIdx.x * (blockDim.x >> 5) + (threadIdx.x >> 5);
    const int nwarp   = gridDim.x * (blockDim.x >> 5);
    const int colbase = lane << 2;
    const float4* wl  = wtab + lane * WSLOTS;

    const float4 wup = wl[20];
    const float  bup = __ldg(b_up);

    int e0 = warp;
    // ---- quad main loop: 8 front-batched 512B loads per warp ----
    for (; e0 + 3 * nwarp < N; e0 += 4 * nwarp) {
        int    ee[4];
        size_t row[4];
        float4 h4[4], c4[4];
        float  gv[4], pv[4], mv[4], uv[4];

        #pragma unroll
        for (int j = 0; j < 4; ++j) {
            ee[j]  = e0 + j * nwarp;
            row[j] = (size_t)ee[j] * HH + colbase;
            h4[j]  = __ldcs(reinterpret_cast<const float4*>(hmat + row[j]));
            c4[j]  = __ldcs(reinterpret_cast<const float4*>(cmat + row[j]));
            gv[j]  = __ldg(grad + ee[j]);
            pv[j]  = __ldg(param + ee[j]);
            mv[j]  = __ldg(momentum + ee[j]);
            uv[j]  = __ldg(prevu + ee[j]);
        }

        #pragma unroll
        for (int j = 0; j < 4; ++j) {
            // gates: z = bs + W_ih @ x
            float zf[16];
            #pragma unroll
            for (int g = 0; g < 4; ++g) {
                const float4 bs = wl[16 + g];
                const float bsk[4] = {bs.x, bs.y, bs.z, bs.w};
                #pragma unroll
                for (int k = 0; k < 4; ++k) {
                    const float4 w = wl[g * 4 + k];
                    float z = bsk[k];
                    z = fmaf(w.x, gv[j], z);
                    z = fmaf(w.y, pv[j], z);
                    z = fmaf(w.z, mv[j], z);
                    z = fmaf(w.w, uv[j], z);
                    zf[g * 4 + k] = z;
                }
            }

            const bool hz = (h4[j].x != 0.0f) || (h4[j].y != 0.0f) ||
                            (h4[j].z != 0.0f) || (h4[j].w != 0.0f);
            if (__any_sync(0xffffffffu, hz))
                add_recurrent(zf, h4[j], W_hh, colbase);

            float4 hn4, cn4;
            float acc = finish_elem(zf, c4[j], wup, hn4, cn4);
            if (out_h != nullptr) {
                __stcs(reinterpret_cast<float4*>(out_h + row[j]), hn4);
                __stcs(reinterpret_cast<float4*>(out_c + row[j]), cn4);
            }
            #pragma unroll
            for (int off = 16; off; off >>= 1)
                acc += __shfl_xor_sync(0xffffffffu, acc, off);
            if (lane == 0) {
                const float upd = acc + bup;
                out_upd[ee[j]] = upd;
                if (out_mom != nullptr) out_mom[ee[j]] = fmaf(0.9f, mv[j], upd);
            }
        }
    }

    // ---- per-element tail ----
    for (; e0 < N; e0 += nwarp) {
        const size_t row = (size_t)e0 * HH + colbase;
        const float4 h4 = __ldcs(reinterpret_cast<const float4*>(hmat + row));
        const float4 c4 = __ldcs(reinterpret_cast<const float4*>(cmat + row));
        const float  gv = __ldg(grad + e0);
        const float  pv = __ldg(param + e0);
        const float  mv = __ldg(momentum + e0);
        const float  uv = __ldg(prevu + e0);

        float zf[16];
        #pragma unroll
        for (int g = 0; g < 4; ++g) {
            const float4 bs = wl[16 + g];
            const float bsk[4] = {bs.x, bs.y, bs.z, bs.w};
            #pragma unroll
            for (int k = 0; k < 4; ++k) {
                const float4 w = wl[g * 4 + k];
                float z = bsk[k];
                z = fmaf(w.x, gv, z);
                z = fmaf(w.y, pv, z);
                z = fmaf(w.z, mv, z);
                z = fmaf(w.w, uv, z);
                zf[g * 4 + k] = z;
            }
        }
        const bool hz = (h4.x != 0.0f) || (h4.y != 0.0f) ||
                        (h4.z != 0.0f) || (h4.w != 0.0f);
        if (__any_sync(0xffffffffu, hz))
            add_recurrent(zf, h4, W_hh, colbase);

        float4 hn4, cn4;
        float acc = finish_elem(zf, c4, wup, hn4, cn4);
        if (out_h != nullptr) {
            __stcs(reinterpret_cast<float4*>(out_h + row), hn4);
            __stcs(reinterpret_cast<float4*>(out_c + row), cn4);
        }
        #pragma unroll
        for (int off = 16; off; off >>= 1)
            acc += __shfl_xor_sync(0xffffffffu, acc, off);
        if (lane == 0) {
            const float upd = acc + bup;
            out_upd[e0] = upd;
            if (out_mom != nullptr) out_mom[e0] = fmaf(0.9f, mv, upd);
        }
    }
}

}  // namespace

extern "C" void kernel_launch(void* const* d_in, const int* in_sizes, int n_in,
                              void* d_out, int out_size) {
    const float* param = (const float*)d_in[0];
    const float* grad  = (const float*)d_in[1];
    const float* h     = (const float*)d_in[2];
    const float* c     = (const float*)d_in[3];
    const float* mom   = (const float*)d_in[4];
    const float* prevu = (const float*)d_in[5];
    const float* W_ih  = (const float*)d_in[6];
    const float* W_hh  = (const float*)d_in[7];
    const float* b_ih  = (const float*)d_in[8];
    const float* b_hh  = (const float*)d_in[9];
    const float* W_up  = (const float*)d_in[10];
    const float* b_up  = (const float*)d_in[11];

    const int N = in_sizes[0];
    float* out = (float*)d_out;

    // Output layout: concat(update, h_new, c_new, momentum_new), reference order.
    float* out_upd = out;
    float* out_h   = nullptr;
    float* out_c   = nullptr;
    float* out_mom = nullptr;
    const long long full = 2LL * N + 2LL * N * 128;
    if ((long long)out_size >= full) {
        out_h   = out + N;
        out_c   = out + N + (size_t)N * 128;
        out_mom = out + N + 2 * (size_t)N * 128;
    } else if (out_size >= 2 * N) {
        out_mom = out + N;
    }

    // 740 = 148 SMs x 5 resident blocks: exactly one full wave at max residency.
    const int threads = 128;
    const int blocks  = 740;
    lstm_opt_kernel<<<blocks, threads>>>(param, grad, h, c, mom, prevu,
                                         W_ih, W_hh, b_ih, b_hh, W_up, b_up,
                                         out_upd, out_h, out_c, out_mom, N);
}

// round 8
// speedup vs baseline: 1.1137x; 1.1137x over previous
#include <cuda_runtime.h>

// LSTMOptimizer: per-element (N=524288) single LSTMCell step (input 4, H=128)
// + Linear(H,1) head. One warp per element-pair; lane owns 4 hidden columns.
//
// R7 = R5 structure (best: 266us) + more resident warps.
// R6 post-mortem: 4-elem quad raised LDS wavefronts 4x (L1 65->85%) and cut
// occupancy -> regression. L1tex wavefront path is the emerging ceiling, so
// keep the lowest-L1-work structure (weights read once per element pair) and
// raise warp count instead:
//  - __launch_bounds__(128,8): regs capped 64, 8 blocks/SM = 32 warps
//  - grid 1184 = 148x8: exactly one full wave
//  - guarded 2-elem main loop + per-element tail (nwarp=4736 !| N)

namespace {

constexpr int HH = 128;
constexpr int WSLOTS = 21;  // float4 slots per lane: 16 W rows + 4 bias + 1 wup

__device__ __forceinline__ float tanhx(float x) {
    float y;
    asm("tanh.approx.f32 %0, %1;" : "=f"(y) : "f"(x));
    return y;
}
__device__ __forceinline__ float sigx(float z) {
    return fmaf(0.5f, tanhx(0.5f * z), 0.5f);
}

// Generic recurrent term (h != 0): exact shuffle-broadcast h @ W_hh.T.
// Warp-uniform entry (guarded by __any_sync result). Rare path.
__device__ __noinline__ void add_recurrent(float zf[16], float4 h4,
                                           const float* __restrict__ W_hh,
                                           int colbase) {
    #pragma unroll 1
    for (int src = 0; src < 32; ++src) {
        const float b0 = __shfl_sync(0xffffffffu, h4.x, src);
        const float b1 = __shfl_sync(0xffffffffu, h4.y, src);
        const float b2 = __shfl_sync(0xffffffffu, h4.z, src);
        const float b3 = __shfl_sync(0xffffffffu, h4.w, src);
        const int kk = src << 2;
        #pragma unroll
        for (int g = 0; g < 4; ++g) {
            #pragma unroll
            for (int k = 0; k < 4; ++k) {
                const float* wr = W_hh + (size_t)(g * HH + colbase + k) * HH + kk;
                float zz = zf[g * 4 + k];
                zz = fmaf(__ldg(wr + 0), b0, zz);
                zz = fmaf(__ldg(wr + 1), b1, zz);
                zz = fmaf(__ldg(wr + 2), b2, zz);
                zz = fmaf(__ldg(wr + 3), b3, zz);
                zf[g * 4 + k] = zz;
            }
        }
    }
}

// Activations + cell/hidden update + head partial dot for one element.
__device__ __forceinline__ float finish_elem(const float zf[16], float4 c4,
                                             float4 wup, float4& hn4, float4& cn4) {
    const float cin[4] = {c4.x, c4.y, c4.z, c4.w};
    const float wuk[4] = {wup.x, wup.y, wup.z, wup.w};
    float hn[4], cn[4];
    float acc = 0.0f;
    #pragma unroll
    for (int k = 0; k < 4; ++k) {
        const float iv = sigx(zf[0 * 4 + k]);
        const float fv = sigx(zf[1 * 4 + k]);
        const float gg = tanhx(zf[2 * 4 + k]);
        const float ov = sigx(zf[3 * 4 + k]);
        const float cc = fmaf(fv, cin[k], iv * gg);
        const float hh = ov * tanhx(cc);
        cn[k] = cc;
        hn[k] = hh;
        acc = fmaf(hh, wuk[k], acc);
    }
    hn4 = make_float4(hn[0], hn[1], hn[2], hn[3]);
    cn4 = make_float4(cn[0], cn[1], cn[2], cn[3]);
    return acc;
}

__global__ void __launch_bounds__(128, 8)
lstm_opt_kernel(const float* __restrict__ param, const float* __restrict__ grad,
                const float* __restrict__ hmat,  const float* __restrict__ cmat,
                const float* __restrict__ momentum, const float* __restrict__ prevu,
                const float* __restrict__ W_ih,  const float* __restrict__ W_hh,
                const float* __restrict__ b_ih,  const float* __restrict__ b_hh,
                const float* __restrict__ W_up,  const float* __restrict__ b_up,
                float* __restrict__ out_upd, float* __restrict__ out_h,
                float* __restrict__ out_c,   float* __restrict__ out_mom,
                int N)
{
    // Per-lane table (float4 slots):
    //   [0..15]  W_ih row (4 floats) for gate-row r = (q>>2)*128 + lane*4 + (q&3)
    //   [16..19] bias sums b_ih[r]+b_hh[r] for the 16 rows (4 per slot)
    //   [20]     W_up[lane*4 .. +3]
    __shared__ float4 wtab[32 * WSLOTS];

    for (int idx = threadIdx.x; idx < 32 * WSLOTS; idx += blockDim.x) {
        const int l = idx / WSLOTS;
        const int q = idx % WSLOTS;
        float4 v;
        if (q < 16) {
            const int r = (q >> 2) * HH + l * 4 + (q & 3);
            v = *reinterpret_cast<const float4*>(W_ih + 4 * r);
        } else if (q < 20) {
            const int g = q - 16;
            const int r0 = g * HH + l * 4;
            v = make_float4(b_ih[r0 + 0] + b_hh[r0 + 0],
                            b_ih[r0 + 1] + b_hh[r0 + 1],
                            b_ih[r0 + 2] + b_hh[r0 + 2],
                            b_ih[r0 + 3] + b_hh[r0 + 3]);
        } else {
            v = *reinterpret_cast<const float4*>(W_up + l * 4);
        }
        wtab[idx] = v;
    }
    __syncthreads();

    const int lane    = threadIdx.x & 31;
    const int warp    = blockIdx.x * (blockDim.x >> 5) + (threadIdx.x >> 5);
    const int nwarp   = gridDim.x * (blockDim.x >> 5);
    const int colbase = lane << 2;
    const float4* wl  = wtab + lane * WSLOTS;

    const float4 wup = wl[20];
    const float  bup = __ldg(b_up);

    int ea = warp;
    // ---- 2-element main loop (weights read once per pair) ----
    for (; ea + nwarp < N; ea += 2 * nwarp) {
        const int eb = ea + nwarp;

        // front-batched loads: 4 independent 512B/warp loads + scalars
        const unsigned rowa = (unsigned)ea * HH + colbase;
        const float4 h4a = __ldcs(reinterpret_cast<const float4*>(hmat + rowa));
        const float4 c4a = __ldcs(reinterpret_cast<const float4*>(cmat + rowa));
        const float  gva = __ldg(grad + ea);
        const float  pva = __ldg(param + ea);
        const float  mva = __ldg(momentum + ea);
        const float  uva = __ldg(prevu + ea);

        const unsigned rowb = (unsigned)eb * HH + colbase;
        const float4 h4b = __ldcs(reinterpret_cast<const float4*>(hmat + rowb));
        const float4 c4b = __ldcs(reinterpret_cast<const float4*>(cmat + rowb));
        const float  gvb = __ldg(grad + eb);
        const float  pvb = __ldg(param + eb);
        const float  mvb = __ldg(momentum + eb);
        const float  uvb = __ldg(prevu + eb);

        // gates: z = bs + W_ih @ x ; weights read once for both elems
        float za[16], zb[16];
        #pragma unroll
        for (int g = 0; g < 4; ++g) {
            const float4 bs = wl[16 + g];
            const float bsk[4] = {bs.x, bs.y, bs.z, bs.w};
            #pragma unroll
            for (int k = 0; k < 4; ++k) {
                const float4 w = wl[g * 4 + k];
                float z = bsk[k];
                z = fmaf(w.x, gva, z);
                z = fmaf(w.y, pva, z);
                z = fmaf(w.z, mva, z);
                z = fmaf(w.w, uva, z);
                za[g * 4 + k] = z;
                z = bsk[k];
                z = fmaf(w.x, gvb, z);
                z = fmaf(w.y, pvb, z);
                z = fmaf(w.z, mvb, z);
                z = fmaf(w.w, uvb, z);
                zb[g * 4 + k] = z;
            }
        }

        // element A
        {
            const bool hz = (h4a.x != 0.0f) || (h4a.y != 0.0f) ||
                            (h4a.z != 0.0f) || (h4a.w != 0.0f);
            if (__any_sync(0xffffffffu, hz))
                add_recurrent(za, h4a, W_hh, colbase);

            float4 hn4, cn4;
            float acc = finish_elem(za, c4a, wup, hn4, cn4);
            if (out_h != nullptr) {
                __stcs(reinterpret_cast<float4*>(out_h + rowa), hn4);
                __stcs(reinterpret_cast<float4*>(out_c + rowa), cn4);
            }
            #pragma unroll
            for (int off = 16; off; off >>= 1)
                acc += __shfl_xor_sync(0xffffffffu, acc, off);
            if (lane == 0) {
                const float upd = acc + bup;
                out_upd[ea] = upd;
                if (out_mom != nullptr) out_mom[ea] = fmaf(0.9f, mva, upd);
            }
        }

        // element B
        {
            const bool hz = (h4b.x != 0.0f) || (h4b.y != 0.0f) ||
                            (h4b.z != 0.0f) || (h4b.w != 0.0f);
            if (__any_sync(0xffffffffu, hz))
                add_recurrent(zb, h4b, W_hh, colbase);

            float4 hn4, cn4;
            float acc = finish_elem(zb, c4b, wup, hn4, cn4);
            if (out_h != nullptr) {
                __stcs(reinterpret_cast<float4*>(out_h + rowb), hn4);
                __stcs(reinterpret_cast<float4*>(out_c + rowb), cn4);
            }
            #pragma unroll
            for (int off = 16; off; off >>= 1)
                acc += __shfl_xor_sync(0xffffffffu, acc, off);
            if (lane == 0) {
                const float upd = acc + bup;
                out_upd[eb] = upd;
                if (out_mom != nullptr) out_mom[eb] = fmaf(0.9f, mvb, upd);
            }
        }
    }

    // ---- per-element tail ----
    for (; ea < N; ea += nwarp) {
        const unsigned row = (unsigned)ea * HH + colbase;
        const float4 h4 = __ldcs(reinterpret_cast<const float4*>(hmat + row));
        const float4 c4 = __ldcs(reinterpret_cast<const float4*>(cmat + row));
        const float  gv = __ldg(grad + ea);
        const float  pv = __ldg(param + ea);
        const float  mv = __ldg(momentum + ea);
        const float  uv = __ldg(prevu + ea);

        float zf[16];
        #pragma unroll
        for (int g = 0; g < 4; ++g) {
            const float4 bs = wl[16 + g];
            const float bsk[4] = {bs.x, bs.y, bs.z, bs.w};
            #pragma unroll
            for (int k = 0; k < 4; ++k) {
                const float4 w = wl[g * 4 + k];
                float z = bsk[k];
                z = fmaf(w.x, gv, z);
                z = fmaf(w.y, pv, z);
                z = fmaf(w.z, mv, z);
                z = fmaf(w.w, uv, z);
                zf[g * 4 + k] = z;
            }
        }
        const bool hz = (h4.x != 0.0f) || (h4.y != 0.0f) ||
                        (h4.z != 0.0f) || (h4.w != 0.0f);
        if (__any_sync(0xffffffffu, hz))
            add_recurrent(zf, h4, W_hh, colbase);

        float4 hn4, cn4;
        float acc = finish_elem(zf, c4, wup, hn4, cn4);
        if (out_h != nullptr) {
            __stcs(reinterpret_cast<float4*>(out_h + row), hn4);
            __stcs(reinterpret_cast<float4*>(out_c + row), cn4);
        }
        #pragma unroll
        for (int off = 16; off; off >>= 1)
            acc += __shfl_xor_sync(0xffffffffu, acc, off);
        if (lane == 0) {
            const float upd = acc + bup;
            out_upd[ea] = upd;
            if (out_mom != nullptr) out_mom[ea] = fmaf(0.9f, mv, upd);
        }
    }
}

}  // namespace

extern "C" void kernel_launch(void* const* d_in, const int* in_sizes, int n_in,
                              void* d_out, int out_size) {
    const float* param = (const float*)d_in[0];
    const float* grad  = (const float*)d_in[1];
    const float* h     = (const float*)d_in[2];
    const float* c     = (const float*)d_in[3];
    const float* mom   = (const float*)d_in[4];
    const float* prevu = (const float*)d_in[5];
    const float* W_ih  = (const float*)d_in[6];
    const float* W_hh  = (const float*)d_in[7];
    const float* b_ih  = (const float*)d_in[8];
    const float* b_hh  = (const float*)d_in[9];
    const float* W_up  = (const float*)d_in[10];
    const float* b_up  = (const float*)d_in[11];

    const int N = in_sizes[0];
    float* out = (float*)d_out;

    // Output layout: concat(update, h_new, c_new, momentum_new), reference order.
    float* out_upd = out;
    float* out_h   = nullptr;
    float* out_c   = nullptr;
    float* out_mom = nullptr;
    const long long full = 2LL * N + 2LL * N * 128;
    if ((long long)out_size >= full) {
        out_h   = out + N;
        out_c   = out + N + (size_t)N * 128;
        out_mom = out + N + 2 * (size_t)N * 128;
    } else if (out_size >= 2 * N) {
        out_mom = out + N;
    }

    // 1184 = 148 SMs x 8 resident blocks: 32 warps/SM, exactly one full wave.
    const int threads = 128;
    const int blocks  = 1184;
    lstm_opt_kernel<<<blocks, threads>>>(param, grad, h, c, mom, prevu,
                                         W_ih, W_hh, b_ih, b_hh, W_up, b_up,
                                         out_upd, out_h, out_c, out_mom, N);
}